// round 1
// baseline (speedup 1.0000x reference)
#include <cuda_runtime.h>
#include <cstdint>

// Problem constants
#define NN   8192     // total points
#define NBV  1024     // points per batch
#define BV   8        // batches
#define KV   9        // kernel taps
#define CV   32       // channels
#define CMV  128      // hidden
#define CWROW 288     // K*C floats per point

// ---------------- static scratch (no allocs allowed) ----------------
__device__ __align__(16) float g_cw[NN * CWROW];        // conv_w, [n][k][c]
__device__ __align__(16) float g_part[2 * NN * CV];     // sampled partials (nb halves)
__device__ __align__(16) float g_xl[NN * CV];           // leaky(sampled)
__device__ __align__(16) float g_x[NN * CV];            // bn1(xl)+weights
__device__ __align__(16) float g_hl[NN * CMV];          // leaky(x@W1+b1)
__device__ float g_s1[CV],  g_s1q[CV];                  // bn1 sums
__device__ float g_s2[CMV], g_s2q[CMV];                 // bn2 sums

// ---------------- K1: conv_w[n][k][c] = sum_d weights[n][d] * KW[k][d][c] ----------------
// grid = 192 blocks (64 n-blocks x 3 k-groups), 128 threads; each thread owns one n row.
__global__ __launch_bounds__(128) void k1_cw(const float* __restrict__ weights,
                                             const float* __restrict__ KW) {
    __shared__ __align__(16) float KWs[3 * CV * CV];   // 12KB: this block's 3 kernels
    __shared__ float tile[128 * 33];                   // transpose bounce, pad 33
    int t    = threadIdx.x;
    int nblk = blockIdx.x / 3;
    int kg   = blockIdx.x % 3;

    for (int i = t; i < 3 * CV * CV; i += 128) KWs[i] = KW[kg * 3 * CV * CV + i];
    __syncthreads();

    int n = nblk * 128 + t;
    float w[CV];
    const float4* wr = reinterpret_cast<const float4*>(&weights[(size_t)n * CV]);
#pragma unroll
    for (int q = 0; q < 8; q++) {
        float4 v = wr[q];
        w[q*4+0]=v.x; w[q*4+1]=v.y; w[q*4+2]=v.z; w[q*4+3]=v.w;
    }

    for (int kk = 0; kk < 3; kk++) {
        float acc[CV];
#pragma unroll
        for (int d = 0; d < CV; d++) acc[d] = 0.f;
#pragma unroll
        for (int c = 0; c < CV; c++) {
            float wc = w[c];
            const float4* kp = reinterpret_cast<const float4*>(&KWs[(kk * CV + c) * CV]);
#pragma unroll
            for (int q = 0; q < 8; q++) {
                float4 v = kp[q];
                acc[q*4+0] += wc * v.x;  acc[q*4+1] += wc * v.y;
                acc[q*4+2] += wc * v.z;  acc[q*4+3] += wc * v.w;
            }
        }
        __syncthreads();   // previous iter's tile readers are done
#pragma unroll
        for (int d = 0; d < CV; d++) tile[t * 33 + d] = acc[d];
        __syncthreads();
        int k = kg * 3 + kk;
        for (int idx = t; idx < 128 * CV; idx += 128) {   // coalesced store
            int nl = idx >> 5, c = idx & 31;
            g_cw[(size_t)(nblk * 128 + nl) * CWROW + k * CV + c] = tile[nl * 33 + c];
        }
    }
}

// ---------------- K2: the heavy fused Kmat*conv_w ----------------
// grid = 8 batches x 8 n-tiles(128) x 2 nb-halves(512) = 128 CTAs, 128 threads.
// Each thread owns one n row and 32 fp32 accumulators.
#define NBT 16
__global__ __launch_bounds__(128) void k2_sample(const float* __restrict__ pos,
                                                 const float* __restrict__ kpos) {
    __shared__ __align__(16) float cwS[NBT * CWROW];   // 18KB
    __shared__ float pS[NBT * 2];

    int t     = threadIdx.x;
    int bid   = blockIdx.x;
    int half  = bid & 1;
    int tileI = (bid >> 1) & 7;
    int b     = bid >> 4;

    int n = b * NBV + tileI * 128 + t;
    float px = pos[2 * n], py = pos[2 * n + 1];

    float gx[KV], gy[KV];
#pragma unroll
    for (int k = 0; k < KV; k++) { gx[k] = kpos[2 * k]; gy[k] = kpos[2 * k + 1]; }

    float acc[CV];
#pragma unroll
    for (int c = 0; c < CV; c++) acc[c] = 0.f;

    int nb0 = b * NBV + half * 512;
    for (int ch = 0; ch < 512; ch += NBT) {
        __syncthreads();
        // stage conv_w rows + neighbor positions for this chunk
        const float4* src = reinterpret_cast<const float4*>(&g_cw[(size_t)(nb0 + ch) * CWROW]);
        float4* dst = reinterpret_cast<float4*>(cwS);
        for (int i = t; i < NBT * (CWROW / 4); i += 128) dst[i] = src[i];
        for (int i = t; i < NBT * 2; i += 128) pS[i] = pos[(size_t)(nb0 + ch) * 2 + i];
        __syncthreads();

#pragma unroll 1
        for (int j = 0; j < NBT; j++) {
            float dX = px - pS[2 * j], dY = py - pS[2 * j + 1];
            float w[KV];
#pragma unroll
            for (int k = 0; k < KV; k++) {
                float ddx = dX - gx[k], ddy = dY - gy[k];
                float d2 = ddx * ddx + ddy * ddy;
                w[k] = __expf(-2.0f * d2);
            }
            const float4* cw4 = reinterpret_cast<const float4*>(&cwS[j * CWROW]);
#pragma unroll
            for (int k = 0; k < KV; k++) {
                float wk = w[k];
#pragma unroll
                for (int q = 0; q < 8; q++) {
                    float4 v = cw4[k * 8 + q];
                    acc[q*4+0] += wk * v.x;  acc[q*4+1] += wk * v.y;
                    acc[q*4+2] += wk * v.z;  acc[q*4+3] += wk * v.w;
                }
            }
        }
    }

    float* outp = &g_part[(size_t)half * NN * CV + (size_t)n * CV];
#pragma unroll
    for (int c = 0; c < CV; c++) outp[c] = acc[c];
}

// ---------------- K3: xl = leaky(part0+part1); per-channel sums (one block per channel) ----------------
__global__ void k3_xl(void) {
    int c = blockIdx.x, t = threadIdx.x;
    float s = 0.f, s2 = 0.f;
    for (int nn = t; nn < NN; nn += 256) {
        float v = g_part[(size_t)nn * CV + c] + g_part[(size_t)NN * CV + (size_t)nn * CV + c];
        float xl = (v >= 0.f) ? v : 0.01f * v;
        g_xl[(size_t)nn * CV + c] = xl;
        s += xl; s2 += xl * xl;
    }
    __shared__ float rs[256], rq[256];
    rs[t] = s; rq[t] = s2; __syncthreads();
    for (int o = 128; o > 0; o >>= 1) {
        if (t < o) { rs[t] += rs[t + o]; rq[t] += rq[t + o]; }
        __syncthreads();
    }
    if (t == 0) { g_s1[c] = rs[0]; g_s1q[c] = rq[0]; }
}

// ---------------- K4: x = bn1(xl)+weights; hl = leaky(x@W1+b1) ----------------
__global__ __launch_bounds__(128) void k4_mlp1(const float* __restrict__ weights,
                                               const float* __restrict__ gamma1,
                                               const float* __restrict__ beta1,
                                               const float* __restrict__ W1,
                                               const float* __restrict__ b1) {
    __shared__ __align__(16) float W1s[CV * CMV];   // 16KB
    __shared__ float sc1[CV], sh1[CV], b1s[CMV];
    int t = threadIdx.x;
    for (int i = t; i < CV * CMV; i += 128) W1s[i] = W1[i];
    if (t < CMV) b1s[t] = b1[t];
    if (t < CV) {
        float mu  = g_s1[t] * (1.0f / NN);
        float var = g_s1q[t] * (1.0f / NN) - mu * mu;
        float inv = rsqrtf(var + 1e-5f);
        float sc  = gamma1[t] * inv;
        sc1[t] = sc; sh1[t] = beta1[t] - mu * sc;
    }
    __syncthreads();

    int n = blockIdx.x * 128 + t;
    float x[CV];
#pragma unroll
    for (int c = 0; c < CV; c++) {
        float xl = g_xl[(size_t)n * CV + c];
        float xv = fmaf(xl, sc1[c], sh1[c]) + weights[(size_t)n * CV + c];
        x[c] = xv;
        g_x[(size_t)n * CV + c] = xv;
    }
#pragma unroll 1
    for (int jb = 0; jb < CMV; jb += 32) {
        float acc[32];
#pragma unroll
        for (int j = 0; j < 32; j++) acc[j] = b1s[jb + j];
#pragma unroll
        for (int c = 0; c < CV; c++) {
            float xc = x[c];
            const float4* wr = reinterpret_cast<const float4*>(&W1s[c * CMV + jb]);
#pragma unroll
            for (int q = 0; q < 8; q++) {
                float4 v = wr[q];
                acc[q*4+0] += xc * v.x;  acc[q*4+1] += xc * v.y;
                acc[q*4+2] += xc * v.z;  acc[q*4+3] += xc * v.w;
            }
        }
#pragma unroll
        for (int j = 0; j < 32; j++) {
            float h = acc[j];
            g_hl[(size_t)n * CMV + jb + j] = (h >= 0.f) ? h : 0.01f * h;
        }
    }
}

// ---------------- K5: bn2 per-channel sums over hl (one block per channel) ----------------
__global__ void k5_stats2(void) {
    int c = blockIdx.x, t = threadIdx.x;
    float s = 0.f, s2 = 0.f;
    for (int nn = t; nn < NN; nn += 256) {
        float v = g_hl[(size_t)nn * CMV + c];
        s += v; s2 += v * v;
    }
    __shared__ float rs[256], rq[256];
    rs[t] = s; rq[t] = s2; __syncthreads();
    for (int o = 128; o > 0; o >>= 1) {
        if (t < o) { rs[t] += rs[t + o]; rq[t] += rq[t + o]; }
        __syncthreads();
    }
    if (t == 0) { g_s2[c] = rs[0]; g_s2q[c] = rq[0]; }
}

// ---------------- K6: h = bn2(hl); mlp_out = h@W2 + b2; write outputs ----------------
__global__ __launch_bounds__(128) void k6_final(const float* __restrict__ pos,
                                                const float* __restrict__ gamma2,
                                                const float* __restrict__ beta2,
                                                const float* __restrict__ W2,
                                                const float* __restrict__ b2,
                                                float* __restrict__ out) {
    __shared__ float W2s[CMV * 34];   // 17.4KB
    __shared__ float sc2[CMV], sh2[CMV], b2s[34];
    int t = threadIdx.x;
    for (int i = t; i < CMV * 34; i += 128) W2s[i] = W2[i];
    if (t < 34) b2s[t] = b2[t];
    if (t < CMV) {
        float mu  = g_s2[t] * (1.0f / NN);
        float var = g_s2q[t] * (1.0f / NN) - mu * mu;
        float inv = rsqrtf(var + 1e-5f);
        float sc  = gamma2[t] * inv;
        sc2[t] = sc; sh2[t] = beta2[t] - mu * sc;
    }
    __syncthreads();

    int n = blockIdx.x * 128 + t;
    float acc[34];
#pragma unroll
    for (int j = 0; j < 34; j++) acc[j] = b2s[j];
#pragma unroll 1
    for (int d = 0; d < CMV; d++) {
        float hv = g_hl[(size_t)n * CMV + d];
        float hn = fmaf(hv, sc2[d], sh2[d]);
        const float* wr = &W2s[d * 34];
#pragma unroll
        for (int j = 0; j < 34; j++) acc[j] += hn * wr[j];
    }

    out[2 * n + 0] = pos[2 * n + 0] + acc[0];
    out[2 * n + 1] = pos[2 * n + 1] + acc[1];
    float* ow = &out[(size_t)NN * 2 + (size_t)n * CV];
#pragma unroll
    for (int c = 0; c < CV; c++) ow[c] = g_x[(size_t)n * CV + c] + acc[2 + c];
}

// ---------------- launch ----------------
extern "C" void kernel_launch(void* const* d_in, const int* in_sizes, int n_in,
                              void* d_out, int out_size) {
    (void)in_sizes; (void)n_in; (void)out_size;
    const float* positions = (const float*)d_in[0];
    const float* weights   = (const float*)d_in[1];
    // d_in[2] = batch (int32, uniform NB) — unused
    const float* kpos      = (const float*)d_in[3];
    const float* KW        = (const float*)d_in[4];
    const float* g1        = (const float*)d_in[5];
    const float* be1       = (const float*)d_in[6];
    const float* W1        = (const float*)d_in[7];
    const float* b1        = (const float*)d_in[8];
    const float* g2        = (const float*)d_in[9];
    const float* be2       = (const float*)d_in[10];
    const float* W2        = (const float*)d_in[11];
    const float* b2        = (const float*)d_in[12];
    float* out = (float*)d_out;

    k1_cw<<<192, 128>>>(weights, KW);
    k2_sample<<<128, 128>>>(positions, kpos);
    k3_xl<<<CV, 256>>>();
    k4_mlp1<<<NN / 128, 128>>>(weights, g1, be1, W1, b1);
    k5_stats2<<<CMV, 256>>>();
    k6_final<<<NN / 128, 128>>>(positions, g2, be2, W2, b2, out);
}